// round 14
// baseline (speedup 1.0000x reference)
#include <cuda_runtime.h>
#include <cuda_bf16.h>
#include <cstdint>

#define B_SZ 1024

// hidden activations, [b][e][j] layout
__device__ float g_h1[B_SZ * 64 * 64];
__device__ float g_h2[B_SZ * 64 * 64];
// W fragment-linear hi/lo tiles, x-fold permutations (see wfrag2)
__device__ __align__(16) uint4 g_Wf0[16 * 1024];
__device__ __align__(16) uint4 g_Wf1[32 * 1024];
// S matrices (direct path)
__device__ float g_S0[B_SZ * 1024];
__device__ float g_S1[B_SZ * 2048];
__device__ float g_S2[B_SZ * 2048];
// k-split partials: [z(16)][b][256]
__device__ float g_part[16 * B_SZ * 256];

__device__ __forceinline__ uint32_t pack_hi(float a, float b) {
    return __byte_perm(__float_as_uint(a), __float_as_uint(b), 0x7632);
}
__device__ __forceinline__ uint32_t pack_lo(float a, float b) {
    float la = a - __uint_as_float(__float_as_uint(a) & 0xFFFF0000u);
    float lb = b - __uint_as_float(__float_as_uint(b) & 0xFFFF0000u);
    uint32_t r;
    asm("cvt.rn.bf16x2.f32 %0, %1, %2;" : "=r"(r) : "f"(lb), "f"(la));
    return r;
}
__device__ __forceinline__ void mma16816(float* c, const uint32_t* a,
                                         uint32_t b0, uint32_t b1) {
    asm volatile(
        "mma.sync.aligned.m16n8k16.row.col.f32.bf16.bf16.f32 "
        "{%0,%1,%2,%3}, {%4,%5,%6,%7}, {%8,%9}, {%0,%1,%2,%3};"
        : "+f"(c[0]), "+f"(c[1]), "+f"(c[2]), "+f"(c[3])
        : "r"(a[0]), "r"(a[1]), "r"(a[2]), "r"(a[3]), "r"(b0), "r"(b1));
}
__device__ __forceinline__ void mma16816_z(float* d, const uint32_t* a,
                                           uint32_t b0, uint32_t b1) {
    float z = 0.f;
    asm volatile(
        "mma.sync.aligned.m16n8k16.row.col.f32.bf16.bf16.f32 "
        "{%0,%1,%2,%3}, {%4,%5,%6,%7}, {%8,%9}, {%10,%11,%12,%13};"
        : "=f"(d[0]), "=f"(d[1]), "=f"(d[2]), "=f"(d[3])
        : "r"(a[0]), "r"(a[1]), "r"(a[2]), "r"(a[3]), "r"(b0), "r"(b1),
          "f"(z), "f"(z), "f"(z), "f"(z));
}

// ---------------------------------------------------------------------------
// W prep, x-fold perms.
// W0 (blocks 0-15):  r = c*64 + (s>>1)*32 + tq*8 + (s&1)*4   (i from s>>1)
// W1 (blocks 16-47): r = c*64 + tq*16 + s*4
// ---------------------------------------------------------------------------
__global__ void __launch_bounds__(256)
wfrag2(const float* __restrict__ W0, const float* __restrict__ W1,
       uint4* __restrict__ o0, uint4* __restrict__ o1) {
    const int blk = blockIdx.x;
    const bool w1 = (blk >= 16);
    const float* W = w1 ? W1 : W0;
    uint4* out     = w1 ? o1 : o0;
    const int c    = w1 ? blk - 16 : blk;
    for (int t = threadIdx.x; t < 1024; t += 256) {
        int s = t >> 8, f = (t >> 5) & 7, lane = t & 31;
        int n = f * 8 + (lane >> 2);
        int tq = lane & 3;
        int r = w1 ? (c * 64 + tq * 16 + s * 4)
                   : (c * 64 + (s >> 1) * 32 + tq * 8 + (s & 1) * 4);
        float w0 = W[(r    ) * 128 + n], w1v = W[(r + 1) * 128 + n];
        float w2 = W[(r + 2) * 128 + n], w3 = W[(r + 3) * 128 + n];
        uint4 o;
        o.x = pack_hi(w0, w1v);
        o.y = pack_hi(w2, w3);
        o.z = pack_lo(w0, w1v);
        o.w = pack_lo(w2, w3);
        out[c * 1024 + t] = o;
    }
}

// ---------------------------------------------------------------------------
// Layer 0 (FI=32), x-fold: A = x[m,j] split once (j-perm j=8tq+4s+u),
// per-i D banks (term-major, spacing 8 alternating banks), acc += x[m,i]*D.
// M-tile=64 (1 batch/CTA), grid=1024, 8 warps = 4m x 2n, 2 CTAs/SM.
// ---------------------------------------------------------------------------
__global__ void __launch_bounds__(256, 2)
cin_mma32(const float* __restrict__ x, const uint4* __restrict__ Wf,
          const float* __restrict__ bias, float* __restrict__ hout)
{
    extern __shared__ char smem[];
    float* xs = (float*)smem;                       // [64][33] fp32, 8448 B
    uint32_t* xhi = (uint32_t*)(smem + 8448);       // [64][20] packed bf16x2
    uint32_t* xlo = (uint32_t*)(smem + 13568);      // [64][20]

    const int tid  = threadIdx.x;
    const int lane = tid & 31;
    const int wid  = tid >> 5;
    const int wm   = wid & 3, wn = wid >> 2;
    const int tq   = lane & 3;
    const int b    = blockIdx.x;

    for (int idx = tid; idx < 2048; idx += 256) {
        int i = idx >> 6, e = idx & 63;
        xs[e * 33 + i] = x[(b * 32 + i) * 64 + e];
    }
    __syncthreads();
    // pack hi/lo from staged xs (no extra global traffic)
#pragma unroll
    for (int r = 0; r < 4; ++r) {
        int idx = tid + r * 256;
        int row = idx >> 4, w = idx & 15;
        float a = xs[row * 33 + 2 * w];
        float b2 = xs[row * 33 + 2 * w + 1];
        xhi[row * 20 + w] = pack_hi(a, b2);
        xlo[row * 20 + w] = pack_lo(a, b2);
    }
    __syncthreads();

    float acc[4][4];
#pragma unroll
    for (int nf = 0; nf < 4; ++nf)
#pragma unroll
        for (int r = 0; r < 4; ++r) acc[nf][r] = 0.f;

    const int ra = wm * 16 + (lane >> 2);   // 0..63
    const int rb = ra + 8;
    const uint4* Wl = Wf + wn * 128 + lane;
    const int wofs = 4 * tq;

    for (int i = 0; i < 32; ++i) {
        const float xa = xs[ra * 33 + i];
        const float xb = xs[rb * 33 + i];
        const uint4* pc = Wl + (size_t)(i >> 1) * 1024 + (i & 1) * 512;

        uint4 B0[4], B1[4];
#pragma unroll
        for (int nf = 0; nf < 4; ++nf) B0[nf] = __ldg(pc + nf * 32);
#pragma unroll
        for (int nf = 0; nf < 4; ++nf) B1[nf] = __ldg(pc + 256 + nf * 32);

        uint4 Ha = *(const uint4*)&xhi[ra * 20 + wofs];
        uint4 Hb = *(const uint4*)&xhi[rb * 20 + wofs];
        uint4 La = *(const uint4*)&xlo[ra * 20 + wofs];
        uint4 Lb = *(const uint4*)&xlo[rb * 20 + wofs];
        uint32_t ah0[4] = { Ha.x, Hb.x, Ha.y, Hb.y };
        uint32_t ah1[4] = { Ha.z, Hb.z, Ha.w, Hb.w };
        uint32_t al0[4] = { La.x, Lb.x, La.y, Lb.y };
        uint32_t al1[4] = { La.z, Lb.z, La.w, Lb.w };

        float D0[4][4], D1[4][4];
        // term hh (zero-init)
#pragma unroll
        for (int nf = 0; nf < 4; ++nf) mma16816_z(D0[nf], ah0, B0[nf].x, B0[nf].y);
#pragma unroll
        for (int nf = 0; nf < 4; ++nf) mma16816_z(D1[nf], ah1, B1[nf].x, B1[nf].y);
        // term hl
#pragma unroll
        for (int nf = 0; nf < 4; ++nf) mma16816(D0[nf], ah0, B0[nf].z, B0[nf].w);
#pragma unroll
        for (int nf = 0; nf < 4; ++nf) mma16816(D1[nf], ah1, B1[nf].z, B1[nf].w);
        // term lh
#pragma unroll
        for (int nf = 0; nf < 4; ++nf) mma16816(D0[nf], al0, B0[nf].x, B0[nf].y);
#pragma unroll
        for (int nf = 0; nf < 4; ++nf) mma16816(D1[nf], al1, B1[nf].x, B1[nf].y);

        // fold: acc += x * (D0 + D1)
#pragma unroll
        for (int nf = 0; nf < 4; ++nf) {
            acc[nf][0] += xa * D0[nf][0]; acc[nf][0] += xa * D1[nf][0];
            acc[nf][1] += xa * D0[nf][1]; acc[nf][1] += xa * D1[nf][1];
            acc[nf][2] += xb * D0[nf][2]; acc[nf][2] += xb * D1[nf][2];
            acc[nf][3] += xb * D0[nf][3]; acc[nf][3] += xb * D1[nf][3];
        }
    }

    // epilogue: hout[b][e][n] = acc + bias
    {
        float* p0 = hout + ((size_t)b * 64 + ra) * 64;
        float* p8 = hout + ((size_t)b * 64 + ra + 8) * 64;
#pragma unroll
        for (int nf = 0; nf < 4; ++nf) {
            const int n = wn * 32 + nf * 8 + tq * 2;
            float bv0 = __ldg(bias + n), bv1 = __ldg(bias + n + 1);
            *(float2*)&p0[n] = make_float2(acc[nf][0] + bv0, acc[nf][1] + bv1);
            *(float2*)&p8[n] = make_float2(acc[nf][2] + bv0, acc[nf][3] + bv1);
        }
    }
}

// ---------------------------------------------------------------------------
// Layer 1 (FI=64), x-fold (unchanged from R13).
// ---------------------------------------------------------------------------
__global__ void __launch_bounds__(256, 2)
cin_mma64(const float* __restrict__ x, const float* __restrict__ h,
          const uint4* __restrict__ Wf, const float* __restrict__ bias,
          float* __restrict__ hout)
{
    extern __shared__ char smem[];
    float* xs = (float*)smem;                        // [64][33]
    uint32_t* hhi = (uint32_t*)(smem + 8448);        // [64][36]
    uint32_t* hlo = (uint32_t*)(smem + 17664);       // [64][36]

    const int tid  = threadIdx.x;
    const int lane = tid & 31;
    const int wid  = tid >> 5;
    const int wm   = wid & 3, wn = wid >> 2;
    const int tq   = lane & 3;
    const int b    = blockIdx.x;

    for (int idx = tid; idx < 2048; idx += 256) {
        int i = idx >> 6, e = idx & 63;
        xs[e * 33 + i] = x[(b * 32 + i) * 64 + e];
    }
#pragma unroll
    for (int r = 0; r < 8; ++r) {
        int idx = tid + r * 256;
        int row = idx >> 5, w = idx & 31;
        float2 v = *(const float2*)&h[((size_t)b * 64 + row) * 64 + 2 * w];
        hhi[row * 36 + w] = pack_hi(v.x, v.y);
        hlo[row * 36 + w] = pack_lo(v.x, v.y);
    }
    __syncthreads();

    float acc[4][4];
#pragma unroll
    for (int nf = 0; nf < 4; ++nf)
#pragma unroll
        for (int r = 0; r < 4; ++r) acc[nf][r] = 0.f;

    const int ra = wm * 16 + (lane >> 2);
    const int rb = ra + 8;
    const uint4* Wl = Wf + wn * 128 + lane;

    for (int c = 0; c < 32; ++c) {
        const float xa = xs[ra * 33 + c];
        const float xb = xs[rb * 33 + c];
        const uint4* pc = Wl + (size_t)c * 1024;

        float D0[4][4], D1[4][4];

#pragma unroll
        for (int sp = 0; sp < 2; ++sp) {
            uint4 B0[4], B1[4];
#pragma unroll
            for (int nf = 0; nf < 4; ++nf) B0[nf] = __ldg(pc + (2 * sp) * 256 + nf * 32);
#pragma unroll
            for (int nf = 0; nf < 4; ++nf) B1[nf] = __ldg(pc + (2 * sp + 1) * 256 + nf * 32);

            const int wofs = 8 * tq + 4 * sp;
            uint4 Ha = *(const uint4*)&hhi[ra * 36 + wofs];
            uint4 Hb = *(const uint4*)&hhi[rb * 36 + wofs];
            uint4 La = *(const uint4*)&hlo[ra * 36 + wofs];
            uint4 Lb = *(const uint4*)&hlo[rb * 36 + wofs];
            uint32_t ah0[4] = { Ha.x, Hb.x, Ha.y, Hb.y };
            uint32_t ah1[4] = { Ha.z, Hb.z, Ha.w, Hb.w };
            uint32_t al0[4] = { La.x, Lb.x, La.y, Lb.y };
            uint32_t al1[4] = { La.z, Lb.z, La.w, Lb.w };

            if (sp == 0) {
#pragma unroll
                for (int nf = 0; nf < 4; ++nf) mma16816_z(D0[nf], ah0, B0[nf].x, B0[nf].y);
#pragma unroll
                for (int nf = 0; nf < 4; ++nf) mma16816_z(D1[nf], ah1, B1[nf].x, B1[nf].y);
            } else {
#pragma unroll
                for (int nf = 0; nf < 4; ++nf) mma16816(D0[nf], ah0, B0[nf].x, B0[nf].y);
#pragma unroll
                for (int nf = 0; nf < 4; ++nf) mma16816(D1[nf], ah1, B1[nf].x, B1[nf].y);
            }
#pragma unroll
            for (int nf = 0; nf < 4; ++nf) mma16816(D0[nf], ah0, B0[nf].z, B0[nf].w);
#pragma unroll
            for (int nf = 0; nf < 4; ++nf) mma16816(D1[nf], ah1, B1[nf].z, B1[nf].w);
#pragma unroll
            for (int nf = 0; nf < 4; ++nf) mma16816(D0[nf], al0, B0[nf].x, B0[nf].y);
#pragma unroll
            for (int nf = 0; nf < 4; ++nf) mma16816(D1[nf], al1, B1[nf].x, B1[nf].y);
        }

#pragma unroll
        for (int nf = 0; nf < 4; ++nf) {
            acc[nf][0] += xa * D0[nf][0]; acc[nf][0] += xa * D1[nf][0];
            acc[nf][1] += xa * D0[nf][1]; acc[nf][1] += xa * D1[nf][1];
            acc[nf][2] += xb * D0[nf][2]; acc[nf][2] += xb * D1[nf][2];
            acc[nf][3] += xb * D0[nf][3]; acc[nf][3] += xb * D1[nf][3];
        }
    }

    {
        float* p0 = hout + ((size_t)b * 64 + ra) * 64;
        float* p8 = hout + ((size_t)b * 64 + ra + 8) * 64;
#pragma unroll
        for (int nf = 0; nf < 4; ++nf) {
            const int n = wn * 32 + nf * 8 + tq * 2;
            float bv0 = __ldg(bias + n), bv1 = __ldg(bias + n + 1);
            *(float2*)&p0[n] = make_float2(acc[nf][0] + bv0, acc[nf][1] + bv1);
            *(float2*)&p8[n] = make_float2(acc[nf][2] + bv0, acc[nf][3] + bv1);
        }
    }
}

// ---------------------------------------------------------------------------
// S kernel: S[b][i*FI+j] = sum_e x[b,i,e]*h[b,j,e].
// ---------------------------------------------------------------------------
template<int FI>
__global__ void __launch_bounds__(256)
skern(const float* __restrict__ x, const float* __restrict__ h,
      float* __restrict__ S)
{
    constexpr int FAN = 32 * FI;
    __shared__ float xs[32 * 65];
    __shared__ float hs[FI * 65];
    const int b = blockIdx.x, tid = threadIdx.x;

    for (int idx = tid; idx < 2048; idx += 256) {
        int i = idx >> 6, e = idx & 63;
        xs[i * 65 + e] = x[(b * 32 + i) * 64 + e];
    }
    if (FI == 32) {
        for (int idx = tid; idx < 2048; idx += 256) {
            int j = idx >> 6, e = idx & 63;
            hs[j * 65 + e] = h[(b * 32 + j) * 64 + e];
        }
    } else {
        for (int idx = tid; idx < 4096; idx += 256) {
            int j = idx & 63, e = idx >> 6;
            hs[j * 65 + e] = h[(b * 64 + e) * 64 + j];
        }
    }
    __syncthreads();

    constexpr int DJ = FI / 16;
    const int i0 = (tid >> 4) * 2;
    const int j0 = (tid & 15) * DJ;

    float acc[2][DJ];
#pragma unroll
    for (int di = 0; di < 2; ++di)
#pragma unroll
        for (int dj = 0; dj < DJ; ++dj) acc[di][dj] = 0.f;

#pragma unroll 4
    for (int e = 0; e < 64; ++e) {
        float x0 = xs[i0 * 65 + e];
        float x1 = xs[(i0 + 1) * 65 + e];
#pragma unroll
        for (int dj = 0; dj < DJ; ++dj) {
            float hv = hs[(j0 + dj) * 65 + e];
            acc[0][dj] += x0 * hv;
            acc[1][dj] += x1 * hv;
        }
    }
#pragma unroll
    for (int di = 0; di < 2; ++di)
#pragma unroll
        for (int dj = 0; dj < DJ; ++dj)
            S[(size_t)b * FAN + (i0 + di) * FI + (j0 + dj)] = acc[di][dj];
}

// ---------------------------------------------------------------------------
// Direct GEMM, deterministic 16-way k-split.
// ---------------------------------------------------------------------------
template<int FAN>
__global__ void __launch_bounds__(256)
dgemm(const float* __restrict__ S, const float* __restrict__ W,
      float* __restrict__ part, int koff, int outoff)
{
    constexpr int KSL = FAN / 16;
    __shared__ float Sm[128 * 68];
    __shared__ float Wt[64 * 33];
    const int tid = threadIdx.x;
    const int m0 = blockIdx.x * 128, n0 = blockIdx.y * 32;
    const int k0 = blockIdx.z * KSL;
    const int ty = tid >> 3, tx = tid & 7;

    float acc[4][4];
#pragma unroll
    for (int r = 0; r < 4; ++r)
#pragma unroll
        for (int cn = 0; cn < 4; ++cn) acc[r][cn] = 0.f;

    for (int kc = 0; kc < KSL; kc += 64) {
        __syncthreads();
#pragma unroll
        for (int r = 0; r < 8; ++r) {
            int idx = tid + r * 256;
            int m = idx >> 4, kq = idx & 15;
            *(float4*)&Sm[m * 68 + kq * 4] =
                *(const float4*)&S[(size_t)(m0 + m) * FAN + k0 + kc + kq * 4];
        }
#pragma unroll
        for (int r = 0; r < 8; ++r) {
            int idx = tid + r * 256;
            int kk = idx >> 5, n = idx & 31;
            Wt[kk * 33 + n] = W[(size_t)(k0 + kc + kk) * 128 + koff + n0 + n];
        }
        __syncthreads();
#pragma unroll 4
        for (int k = 0; k < 64; ++k) {
            float a[4], bb[4];
#pragma unroll
            for (int r = 0; r < 4; ++r) a[r] = Sm[(ty * 4 + r) * 68 + k];
#pragma unroll
            for (int cn = 0; cn < 4; ++cn) bb[cn] = Wt[k * 33 + tx * 4 + cn];
#pragma unroll
            for (int r = 0; r < 4; ++r)
#pragma unroll
                for (int cn = 0; cn < 4; ++cn) acc[r][cn] += a[r] * bb[cn];
        }
    }

    float* pb = part + ((size_t)blockIdx.z * B_SZ) * 256;
#pragma unroll
    for (int r = 0; r < 4; ++r)
#pragma unroll
        for (int cn = 0; cn < 4; ++cn)
            pb[(size_t)(m0 + ty * 4 + r) * 256 + outoff + n0 + tx * 4 + cn] = acc[r][cn];
}

// ---------------------------------------------------------------------------
__global__ void __launch_bounds__(256)
reduce_out(const float* __restrict__ part, const float* __restrict__ b0,
           const float* __restrict__ b1, const float* __restrict__ b2,
           float* __restrict__ out)
{
    const int b = blockIdx.x, c = threadIdx.x;
    float v = (c < 64) ? b0[64 + c] : (c < 128) ? b1[c] : b2[c - 128];
    float s = 64.0f * v;
#pragma unroll
    for (int z = 0; z < 16; ++z)
        s += part[((size_t)z * B_SZ + b) * 256 + c];
    out[b * 256 + c] = s;
}

// ---------------------------------------------------------------------------
// Side streams for tail overlap (created at load; graph-capture safe).
// ---------------------------------------------------------------------------
struct AuxStreams {
    cudaStream_t s1 = 0, s2 = 0;
    cudaEvent_t ev0 = 0, ev1 = 0, ej1 = 0, ej2 = 0;
    bool ok = false;
    AuxStreams() {
        ok = cudaStreamCreateWithFlags(&s1, cudaStreamNonBlocking) == cudaSuccess
          && cudaStreamCreateWithFlags(&s2, cudaStreamNonBlocking) == cudaSuccess
          && cudaEventCreateWithFlags(&ev0, cudaEventDisableTiming) == cudaSuccess
          && cudaEventCreateWithFlags(&ev1, cudaEventDisableTiming) == cudaSuccess
          && cudaEventCreateWithFlags(&ej1, cudaEventDisableTiming) == cudaSuccess
          && cudaEventCreateWithFlags(&ej2, cudaEventDisableTiming) == cudaSuccess;
    }
};
static AuxStreams g_aux;

// ---------------------------------------------------------------------------
extern "C" void kernel_launch(void* const* d_in, const int* in_sizes, int n_in,
                              void* d_out, int out_size)
{
    const float* x  = (const float*)d_in[0];
    const float* W0 = (const float*)d_in[1];
    const float* b0 = (const float*)d_in[2];
    const float* W1 = (const float*)d_in[3];
    const float* b1 = (const float*)d_in[4];
    const float* W2 = (const float*)d_in[5];
    const float* b2 = (const float*)d_in[6];
    float* out = (float*)d_out;

    float *h1p, *h2p, *s0p, *s1p, *s2p, *pp;
    uint4 *wf0, *wf1;
    cudaGetSymbolAddress((void**)&h1p, g_h1);
    cudaGetSymbolAddress((void**)&h2p, g_h2);
    cudaGetSymbolAddress((void**)&wf0, g_Wf0);
    cudaGetSymbolAddress((void**)&wf1, g_Wf1);
    cudaGetSymbolAddress((void**)&s0p, g_S0);
    cudaGetSymbolAddress((void**)&s1p, g_S1);
    cudaGetSymbolAddress((void**)&s2p, g_S2);
    cudaGetSymbolAddress((void**)&pp,  g_part);

    const int smM32 = 8448 + 5120 * 2; // 18688 B
    const int smM64 = 8448 + 9216 * 2; // 26880 B
    cudaFuncSetAttribute(cin_mma32, cudaFuncAttributeMaxDynamicSharedMemorySize, smM32);
    cudaFuncSetAttribute(cin_mma64, cudaFuncAttributeMaxDynamicSharedMemorySize, smM64);

    if (g_aux.ok) {
        // fork: layer-0 direct path (needs only x, W0)
        cudaEventRecord(g_aux.ev0, 0);
        cudaStreamWaitEvent(g_aux.s1, g_aux.ev0, 0);
        skern<32><<<B_SZ, 256, 0, g_aux.s1>>>(x, x, s0p);
        dgemm<1024><<<dim3(8, 2, 16), 256, 0, g_aux.s1>>>(s0p, W0, pp, 64, 0);
        cudaEventRecord(g_aux.ej1, g_aux.s1);

        wfrag2<<<48, 256>>>(W0, W1, wf0, wf1);
        cin_mma32<<<B_SZ, 256, smM32>>>(x, wf0, b0, h1p);

        // fork: layer-1 direct path (needs h1)
        cudaEventRecord(g_aux.ev1, 0);
        cudaStreamWaitEvent(g_aux.s2, g_aux.ev1, 0);
        skern<64><<<B_SZ, 256, 0, g_aux.s2>>>(x, h1p, s1p);
        dgemm<2048><<<dim3(8, 2, 16), 256, 0, g_aux.s2>>>(s1p, W1, pp, 64, 64);
        cudaEventRecord(g_aux.ej2, g_aux.s2);

        cin_mma64<<<B_SZ, 256, smM64>>>(x, h1p, wf1, b1, h2p);
        skern<64><<<B_SZ, 256>>>(x, h2p, s2p);
        dgemm<2048><<<dim3(8, 4, 16), 256>>>(s2p, W2, pp, 0, 128);

        // join
        cudaStreamWaitEvent(0, g_aux.ej1, 0);
        cudaStreamWaitEvent(0, g_aux.ej2, 0);
        reduce_out<<<B_SZ, 256>>>(pp, b0, b1, b2, out);
    } else {
        wfrag2<<<48, 256>>>(W0, W1, wf0, wf1);
        cin_mma32<<<B_SZ, 256, smM32>>>(x, wf0, b0, h1p);
        cin_mma64<<<B_SZ, 256, smM64>>>(x, h1p, wf1, b1, h2p);
        skern<32><<<B_SZ, 256>>>(x, x, s0p);
        skern<64><<<B_SZ, 256>>>(x, h1p, s1p);
        skern<64><<<B_SZ, 256>>>(x, h2p, s2p);
        dgemm<1024><<<dim3(8, 2, 16), 256>>>(s0p, W0, pp, 64, 0);
        dgemm<2048><<<dim3(8, 2, 16), 256>>>(s1p, W1, pp, 64, 64);
        dgemm<2048><<<dim3(8, 4, 16), 256>>>(s2p, W2, pp, 0, 128);
        reduce_out<<<B_SZ, 256>>>(pp, b0, b1, b2, out);
    }
}

// round 15
// speedup vs baseline: 1.1270x; 1.1270x over previous
#include <cuda_runtime.h>
#include <cuda_bf16.h>
#include <cstdint>

#define B_SZ 1024

__device__ float g_h1[B_SZ * 64 * 64];
__device__ float g_h2[B_SZ * 64 * 64];
__device__ __align__(16) uint4 g_Wf0[16 * 1024];
__device__ __align__(16) uint4 g_Wf1[32 * 1024];
__device__ float g_S0[B_SZ * 1024];
__device__ float g_S1[B_SZ * 2048];
__device__ float g_S2[B_SZ * 2048];
__device__ float g_part[16 * B_SZ * 256];

__device__ __forceinline__ uint32_t pack_hi(float a, float b) {
    return __byte_perm(__float_as_uint(a), __float_as_uint(b), 0x7632);
}
__device__ __forceinline__ uint32_t pack_lo(float a, float b) {
    float la = a - __uint_as_float(__float_as_uint(a) & 0xFFFF0000u);
    float lb = b - __uint_as_float(__float_as_uint(b) & 0xFFFF0000u);
    uint32_t r;
    asm("cvt.rn.bf16x2.f32 %0, %1, %2;" : "=r"(r) : "f"(lb), "f"(la));
    return r;
}
__device__ __forceinline__ void mma16816(float* c, const uint32_t* a,
                                         uint32_t b0, uint32_t b1) {
    asm volatile(
        "mma.sync.aligned.m16n8k16.row.col.f32.bf16.bf16.f32 "
        "{%0,%1,%2,%3}, {%4,%5,%6,%7}, {%8,%9}, {%0,%1,%2,%3};"
        : "+f"(c[0]), "+f"(c[1]), "+f"(c[2]), "+f"(c[3])
        : "r"(a[0]), "r"(a[1]), "r"(a[2]), "r"(a[3]), "r"(b0), "r"(b1));
}
__device__ __forceinline__ void mma16816_z(float* d, const uint32_t* a,
                                           uint32_t b0, uint32_t b1) {
    float z = 0.f;
    asm volatile(
        "mma.sync.aligned.m16n8k16.row.col.f32.bf16.bf16.f32 "
        "{%0,%1,%2,%3}, {%4,%5,%6,%7}, {%8,%9}, {%10,%11,%12,%13};"
        : "=f"(d[0]), "=f"(d[1]), "=f"(d[2]), "=f"(d[3])
        : "r"(a[0]), "r"(a[1]), "r"(a[2]), "r"(a[3]), "r"(b0), "r"(b1),
          "f"(z), "f"(z), "f"(z), "f"(z));
}

// ---------------------------------------------------------------------------
// W prep, x-fold perms (identical to R14).
// W0 (blocks 0-15):  r = c*64 + (s>>1)*32 + tq*8 + (s&1)*4
// W1 (blocks 16-47): r = c*64 + tq*16 + s*4
// ---------------------------------------------------------------------------
__global__ void __launch_bounds__(256)
wfrag2(const float* __restrict__ W0, const float* __restrict__ W1,
       uint4* __restrict__ o0, uint4* __restrict__ o1) {
    const int blk = blockIdx.x;
    const bool w1 = (blk >= 16);
    const float* W = w1 ? W1 : W0;
    uint4* out     = w1 ? o1 : o0;
    const int c    = w1 ? blk - 16 : blk;
    for (int t = threadIdx.x; t < 1024; t += 256) {
        int s = t >> 8, f = (t >> 5) & 7, lane = t & 31;
        int n = f * 8 + (lane >> 2);
        int tq = lane & 3;
        int r = w1 ? (c * 64 + tq * 16 + s * 4)
                   : (c * 64 + (s >> 1) * 32 + tq * 8 + (s & 1) * 4);
        float w0 = W[(r    ) * 128 + n], w1v = W[(r + 1) * 128 + n];
        float w2 = W[(r + 2) * 128 + n], w3 = W[(r + 3) * 128 + n];
        uint4 o;
        o.x = pack_hi(w0, w1v);
        o.y = pack_hi(w2, w3);
        o.z = pack_lo(w0, w1v);
        o.w = pack_lo(w2, w3);
        out[c * 1024 + t] = o;
    }
}

// ---------------------------------------------------------------------------
// Layer 0 (FI=32), x-fold with HOISTED loop-invariant A fragments.
// ---------------------------------------------------------------------------
__global__ void __launch_bounds__(256, 2)
cin_mma32(const float* __restrict__ x, const uint4* __restrict__ Wf,
          const float* __restrict__ bias, float* __restrict__ hout)
{
    extern __shared__ char smem[];
    float* xs = (float*)smem;                       // [64][33]
    uint32_t* xhi = (uint32_t*)(smem + 8448);       // [64][20]
    uint32_t* xlo = (uint32_t*)(smem + 13568);      // [64][20]

    const int tid  = threadIdx.x;
    const int lane = tid & 31;
    const int wid  = tid >> 5;
    const int wm   = wid & 3, wn = wid >> 2;
    const int tq   = lane & 3;
    const int b    = blockIdx.x;

    for (int idx = tid; idx < 2048; idx += 256) {
        int i = idx >> 6, e = idx & 63;
        xs[e * 33 + i] = x[(b * 32 + i) * 64 + e];
    }
    __syncthreads();
#pragma unroll
    for (int r = 0; r < 4; ++r) {
        int idx = tid + r * 256;
        int row = idx >> 4, w = idx & 15;
        float a = xs[row * 33 + 2 * w];
        float b2 = xs[row * 33 + 2 * w + 1];
        xhi[row * 20 + w] = pack_hi(a, b2);
        xlo[row * 20 + w] = pack_lo(a, b2);
    }
    __syncthreads();

    float acc[4][4];
#pragma unroll
    for (int nf = 0; nf < 4; ++nf)
#pragma unroll
        for (int r = 0; r < 4; ++r) acc[nf][r] = 0.f;

    const int ra = wm * 16 + (lane >> 2);
    const int rb = ra + 8;
    const uint4* Wl = Wf + wn * 128 + lane;
    const int wofs = 4 * tq;

    // ---- hoisted loop-invariant A fragments ----
    uint32_t ah0[4], ah1[4], al0[4], al1[4];
    {
        uint4 Ha = *(const uint4*)&xhi[ra * 20 + wofs];
        uint4 Hb = *(const uint4*)&xhi[rb * 20 + wofs];
        uint4 La = *(const uint4*)&xlo[ra * 20 + wofs];
        uint4 Lb = *(const uint4*)&xlo[rb * 20 + wofs];
        ah0[0] = Ha.x; ah0[1] = Hb.x; ah0[2] = Ha.y; ah0[3] = Hb.y;
        ah1[0] = Ha.z; ah1[1] = Hb.z; ah1[2] = Ha.w; ah1[3] = Hb.w;
        al0[0] = La.x; al0[1] = Lb.x; al0[2] = La.y; al0[3] = Lb.y;
        al1[0] = La.z; al1[1] = Lb.z; al1[2] = La.w; al1[3] = Lb.w;
    }

    for (int i = 0; i < 32; ++i) {
        const float xa = xs[ra * 33 + i];
        const float xb = xs[rb * 33 + i];
        const uint4* pc = Wl + (size_t)(i >> 1) * 1024 + (i & 1) * 512;

        uint4 B0[4], B1[4];
#pragma unroll
        for (int nf = 0; nf < 4; ++nf) B0[nf] = __ldg(pc + nf * 32);
#pragma unroll
        for (int nf = 0; nf < 4; ++nf) B1[nf] = __ldg(pc + 256 + nf * 32);

        float D0[4][4], D1[4][4];
#pragma unroll
        for (int nf = 0; nf < 4; ++nf) mma16816_z(D0[nf], ah0, B0[nf].x, B0[nf].y);
#pragma unroll
        for (int nf = 0; nf < 4; ++nf) mma16816_z(D1[nf], ah1, B1[nf].x, B1[nf].y);
#pragma unroll
        for (int nf = 0; nf < 4; ++nf) mma16816(D0[nf], ah0, B0[nf].z, B0[nf].w);
#pragma unroll
        for (int nf = 0; nf < 4; ++nf) mma16816(D1[nf], ah1, B1[nf].z, B1[nf].w);
#pragma unroll
        for (int nf = 0; nf < 4; ++nf) mma16816(D0[nf], al0, B0[nf].x, B0[nf].y);
#pragma unroll
        for (int nf = 0; nf < 4; ++nf) mma16816(D1[nf], al1, B1[nf].x, B1[nf].y);

#pragma unroll
        for (int nf = 0; nf < 4; ++nf) {
            acc[nf][0] += xa * D0[nf][0]; acc[nf][0] += xa * D1[nf][0];
            acc[nf][1] += xa * D0[nf][1]; acc[nf][1] += xa * D1[nf][1];
            acc[nf][2] += xb * D0[nf][2]; acc[nf][2] += xb * D1[nf][2];
            acc[nf][3] += xb * D0[nf][3]; acc[nf][3] += xb * D1[nf][3];
        }
    }

    {
        float* p0 = hout + ((size_t)b * 64 + ra) * 64;
        float* p8 = hout + ((size_t)b * 64 + ra + 8) * 64;
#pragma unroll
        for (int nf = 0; nf < 4; ++nf) {
            const int n = wn * 32 + nf * 8 + tq * 2;
            float bv0 = __ldg(bias + n), bv1 = __ldg(bias + n + 1);
            *(float2*)&p0[n] = make_float2(acc[nf][0] + bv0, acc[nf][1] + bv1);
            *(float2*)&p8[n] = make_float2(acc[nf][2] + bv0, acc[nf][3] + bv1);
        }
    }
}

// ---------------------------------------------------------------------------
// Layer 1 (FI=64), x-fold with HOISTED loop-invariant A fragments (2 sp sets).
// ---------------------------------------------------------------------------
__global__ void __launch_bounds__(256, 2)
cin_mma64(const float* __restrict__ x, const float* __restrict__ h,
          const uint4* __restrict__ Wf, const float* __restrict__ bias,
          float* __restrict__ hout)
{
    extern __shared__ char smem[];
    float* xs = (float*)smem;                        // [64][33]
    uint32_t* hhi = (uint32_t*)(smem + 8448);        // [64][36]
    uint32_t* hlo = (uint32_t*)(smem + 17664);       // [64][36]

    const int tid  = threadIdx.x;
    const int lane = tid & 31;
    const int wid  = tid >> 5;
    const int wm   = wid & 3, wn = wid >> 2;
    const int tq   = lane & 3;
    const int b    = blockIdx.x;

    for (int idx = tid; idx < 2048; idx += 256) {
        int i = idx >> 6, e = idx & 63;
        xs[e * 33 + i] = x[(b * 32 + i) * 64 + e];
    }
#pragma unroll
    for (int r = 0; r < 8; ++r) {
        int idx = tid + r * 256;
        int row = idx >> 5, w = idx & 31;
        float2 v = *(const float2*)&h[((size_t)b * 64 + row) * 64 + 2 * w];
        hhi[row * 36 + w] = pack_hi(v.x, v.y);
        hlo[row * 36 + w] = pack_lo(v.x, v.y);
    }
    __syncthreads();

    float acc[4][4];
#pragma unroll
    for (int nf = 0; nf < 4; ++nf)
#pragma unroll
        for (int r = 0; r < 4; ++r) acc[nf][r] = 0.f;

    const int ra = wm * 16 + (lane >> 2);
    const int rb = ra + 8;
    const uint4* Wl = Wf + wn * 128 + lane;

    // ---- hoisted loop-invariant A fragments: [sp][ksub][4] ----
    uint32_t ah[2][2][4], al[2][2][4];
#pragma unroll
    for (int sp = 0; sp < 2; ++sp) {
        const int wofs = 8 * tq + 4 * sp;
        uint4 Ha = *(const uint4*)&hhi[ra * 36 + wofs];
        uint4 Hb = *(const uint4*)&hhi[rb * 36 + wofs];
        uint4 La = *(const uint4*)&hlo[ra * 36 + wofs];
        uint4 Lb = *(const uint4*)&hlo[rb * 36 + wofs];
        ah[sp][0][0] = Ha.x; ah[sp][0][1] = Hb.x; ah[sp][0][2] = Ha.y; ah[sp][0][3] = Hb.y;
        ah[sp][1][0] = Ha.z; ah[sp][1][1] = Hb.z; ah[sp][1][2] = Ha.w; ah[sp][1][3] = Hb.w;
        al[sp][0][0] = La.x; al[sp][0][1] = Lb.x; al[sp][0][2] = La.y; al[sp][0][3] = Lb.y;
        al[sp][1][0] = La.z; al[sp][1][1] = Lb.z; al[sp][1][2] = La.w; al[sp][1][3] = Lb.w;
    }

    for (int c = 0; c < 32; ++c) {
        const float xa = xs[ra * 33 + c];
        const float xb = xs[rb * 33 + c];
        const uint4* pc = Wl + (size_t)c * 1024;

        float D0[4][4], D1[4][4];

#pragma unroll
        for (int sp = 0; sp < 2; ++sp) {
            uint4 B0[4], B1[4];
#pragma unroll
            for (int nf = 0; nf < 4; ++nf) B0[nf] = __ldg(pc + (2 * sp) * 256 + nf * 32);
#pragma unroll
            for (int nf = 0; nf < 4; ++nf) B1[nf] = __ldg(pc + (2 * sp + 1) * 256 + nf * 32);

            if (sp == 0) {
#pragma unroll
                for (int nf = 0; nf < 4; ++nf) mma16816_z(D0[nf], ah[0][0], B0[nf].x, B0[nf].y);
#pragma unroll
                for (int nf = 0; nf < 4; ++nf) mma16816_z(D1[nf], ah[0][1], B1[nf].x, B1[nf].y);
            } else {
#pragma unroll
                for (int nf = 0; nf < 4; ++nf) mma16816(D0[nf], ah[1][0], B0[nf].x, B0[nf].y);
#pragma unroll
                for (int nf = 0; nf < 4; ++nf) mma16816(D1[nf], ah[1][1], B1[nf].x, B1[nf].y);
            }
#pragma unroll
            for (int nf = 0; nf < 4; ++nf) mma16816(D0[nf], ah[sp][0], B0[nf].z, B0[nf].w);
#pragma unroll
            for (int nf = 0; nf < 4; ++nf) mma16816(D1[nf], ah[sp][1], B1[nf].z, B1[nf].w);
#pragma unroll
            for (int nf = 0; nf < 4; ++nf) mma16816(D0[nf], al[sp][0], B0[nf].x, B0[nf].y);
#pragma unroll
            for (int nf = 0; nf < 4; ++nf) mma16816(D1[nf], al[sp][1], B1[nf].x, B1[nf].y);
        }

#pragma unroll
        for (int nf = 0; nf < 4; ++nf) {
            acc[nf][0] += xa * D0[nf][0]; acc[nf][0] += xa * D1[nf][0];
            acc[nf][1] += xa * D0[nf][1]; acc[nf][1] += xa * D1[nf][1];
            acc[nf][2] += xb * D0[nf][2]; acc[nf][2] += xb * D1[nf][2];
            acc[nf][3] += xb * D0[nf][3]; acc[nf][3] += xb * D1[nf][3];
        }
    }

    {
        float* p0 = hout + ((size_t)b * 64 + ra) * 64;
        float* p8 = hout + ((size_t)b * 64 + ra + 8) * 64;
#pragma unroll
        for (int nf = 0; nf < 4; ++nf) {
            const int n = wn * 32 + nf * 8 + tq * 2;
            float bv0 = __ldg(bias + n), bv1 = __ldg(bias + n + 1);
            *(float2*)&p0[n] = make_float2(acc[nf][0] + bv0, acc[nf][1] + bv1);
            *(float2*)&p8[n] = make_float2(acc[nf][2] + bv0, acc[nf][3] + bv1);
        }
    }
}

// ---------------------------------------------------------------------------
template<int FI>
__global__ void __launch_bounds__(256)
skern(const float* __restrict__ x, const float* __restrict__ h,
      float* __restrict__ S)
{
    constexpr int FAN = 32 * FI;
    __shared__ float xs[32 * 65];
    __shared__ float hs[FI * 65];
    const int b = blockIdx.x, tid = threadIdx.x;

    for (int idx = tid; idx < 2048; idx += 256) {
        int i = idx >> 6, e = idx & 63;
        xs[i * 65 + e] = x[(b * 32 + i) * 64 + e];
    }
    if (FI == 32) {
        for (int idx = tid; idx < 2048; idx += 256) {
            int j = idx >> 6, e = idx & 63;
            hs[j * 65 + e] = h[(b * 32 + j) * 64 + e];
        }
    } else {
        for (int idx = tid; idx < 4096; idx += 256) {
            int j = idx & 63, e = idx >> 6;
            hs[j * 65 + e] = h[(b * 64 + e) * 64 + j];
        }
    }
    __syncthreads();

    constexpr int DJ = FI / 16;
    const int i0 = (tid >> 4) * 2;
    const int j0 = (tid & 15) * DJ;

    float acc[2][DJ];
#pragma unroll
    for (int di = 0; di < 2; ++di)
#pragma unroll
        for (int dj = 0; dj < DJ; ++dj) acc[di][dj] = 0.f;

#pragma unroll 4
    for (int e = 0; e < 64; ++e) {
        float x0 = xs[i0 * 65 + e];
        float x1 = xs[(i0 + 1) * 65 + e];
#pragma unroll
        for (int dj = 0; dj < DJ; ++dj) {
            float hv = hs[(j0 + dj) * 65 + e];
            acc[0][dj] += x0 * hv;
            acc[1][dj] += x1 * hv;
        }
    }
#pragma unroll
    for (int di = 0; di < 2; ++di)
#pragma unroll
        for (int dj = 0; dj < DJ; ++dj)
            S[(size_t)b * FAN + (i0 + di) * FI + (j0 + dj)] = acc[di][dj];
}

// ---------------------------------------------------------------------------
template<int FAN>
__global__ void __launch_bounds__(256)
dgemm(const float* __restrict__ S, const float* __restrict__ W,
      float* __restrict__ part, int koff, int outoff)
{
    constexpr int KSL = FAN / 16;
    __shared__ float Sm[128 * 68];
    __shared__ float Wt[64 * 33];
    const int tid = threadIdx.x;
    const int m0 = blockIdx.x * 128, n0 = blockIdx.y * 32;
    const int k0 = blockIdx.z * KSL;
    const int ty = tid >> 3, tx = tid & 7;

    float acc[4][4];
#pragma unroll
    for (int r = 0; r < 4; ++r)
#pragma unroll
        for (int cn = 0; cn < 4; ++cn) acc[r][cn] = 0.f;

    for (int kc = 0; kc < KSL; kc += 64) {
        __syncthreads();
#pragma unroll
        for (int r = 0; r < 8; ++r) {
            int idx = tid + r * 256;
            int m = idx >> 4, kq = idx & 15;
            *(float4*)&Sm[m * 68 + kq * 4] =
                *(const float4*)&S[(size_t)(m0 + m) * FAN + k0 + kc + kq * 4];
        }
#pragma unroll
        for (int r = 0; r < 8; ++r) {
            int idx = tid + r * 256;
            int kk = idx >> 5, n = idx & 31;
            Wt[kk * 33 + n] = W[(size_t)(k0 + kc + kk) * 128 + koff + n0 + n];
        }
        __syncthreads();
#pragma unroll 4
        for (int k = 0; k < 64; ++k) {
            float a[4], bb[4];
#pragma unroll
            for (int r = 0; r < 4; ++r) a[r] = Sm[(ty * 4 + r) * 68 + k];
#pragma unroll
            for (int cn = 0; cn < 4; ++cn) bb[cn] = Wt[k * 33 + tx * 4 + cn];
#pragma unroll
            for (int r = 0; r < 4; ++r)
#pragma unroll
                for (int cn = 0; cn < 4; ++cn) acc[r][cn] += a[r] * bb[cn];
        }
    }

    float* pb = part + ((size_t)blockIdx.z * B_SZ) * 256;
#pragma unroll
    for (int r = 0; r < 4; ++r)
#pragma unroll
        for (int cn = 0; cn < 4; ++cn)
            pb[(size_t)(m0 + ty * 4 + r) * 256 + outoff + n0 + tx * 4 + cn] = acc[r][cn];
}

// ---------------------------------------------------------------------------
__global__ void __launch_bounds__(256)
reduce_out(const float* __restrict__ part, const float* __restrict__ b0,
           const float* __restrict__ b1, const float* __restrict__ b2,
           float* __restrict__ out)
{
    const int b = blockIdx.x, c = threadIdx.x;
    float v = (c < 64) ? b0[64 + c] : (c < 128) ? b1[c] : b2[c - 128];
    float s = 64.0f * v;
#pragma unroll
    for (int z = 0; z < 16; ++z)
        s += part[((size_t)z * B_SZ + b) * 256 + c];
    out[b * 256 + c] = s;
}

// ---------------------------------------------------------------------------
struct AuxStreams {
    cudaStream_t s1 = 0, s2 = 0;
    cudaEvent_t ev0 = 0, ev1 = 0, ej1 = 0, ej2 = 0;
    bool ok = false;
    AuxStreams() {
        ok = cudaStreamCreateWithFlags(&s1, cudaStreamNonBlocking) == cudaSuccess
          && cudaStreamCreateWithFlags(&s2, cudaStreamNonBlocking) == cudaSuccess
          && cudaEventCreateWithFlags(&ev0, cudaEventDisableTiming) == cudaSuccess
          && cudaEventCreateWithFlags(&ev1, cudaEventDisableTiming) == cudaSuccess
          && cudaEventCreateWithFlags(&ej1, cudaEventDisableTiming) == cudaSuccess
          && cudaEventCreateWithFlags(&ej2, cudaEventDisableTiming) == cudaSuccess;
    }
};
static AuxStreams g_aux;

// ---------------------------------------------------------------------------
extern "C" void kernel_launch(void* const* d_in, const int* in_sizes, int n_in,
                              void* d_out, int out_size)
{
    const float* x  = (const float*)d_in[0];
    const float* W0 = (const float*)d_in[1];
    const float* b0 = (const float*)d_in[2];
    const float* W1 = (const float*)d_in[3];
    const float* b1 = (const float*)d_in[4];
    const float* W2 = (const float*)d_in[5];
    const float* b2 = (const float*)d_in[6];
    float* out = (float*)d_out;

    float *h1p, *h2p, *s0p, *s1p, *s2p, *pp;
    uint4 *wf0, *wf1;
    cudaGetSymbolAddress((void**)&h1p, g_h1);
    cudaGetSymbolAddress((void**)&h2p, g_h2);
    cudaGetSymbolAddress((void**)&wf0, g_Wf0);
    cudaGetSymbolAddress((void**)&wf1, g_Wf1);
    cudaGetSymbolAddress((void**)&s0p, g_S0);
    cudaGetSymbolAddress((void**)&s1p, g_S1);
    cudaGetSymbolAddress((void**)&s2p, g_S2);
    cudaGetSymbolAddress((void**)&pp,  g_part);

    const int smM32 = 8448 + 5120 * 2; // 18688 B
    const int smM64 = 8448 + 9216 * 2; // 26880 B
    cudaFuncSetAttribute(cin_mma32, cudaFuncAttributeMaxDynamicSharedMemorySize, smM32);
    cudaFuncSetAttribute(cin_mma64, cudaFuncAttributeMaxDynamicSharedMemorySize, smM64);

    if (g_aux.ok) {
        cudaEventRecord(g_aux.ev0, 0);
        cudaStreamWaitEvent(g_aux.s1, g_aux.ev0, 0);
        skern<32><<<B_SZ, 256, 0, g_aux.s1>>>(x, x, s0p);
        dgemm<1024><<<dim3(8, 2, 16), 256, 0, g_aux.s1>>>(s0p, W0, pp, 64, 0);
        cudaEventRecord(g_aux.ej1, g_aux.s1);

        wfrag2<<<48, 256>>>(W0, W1, wf0, wf1);
        cin_mma32<<<B_SZ, 256, smM32>>>(x, wf0, b0, h1p);

        cudaEventRecord(g_aux.ev1, 0);
        cudaStreamWaitEvent(g_aux.s2, g_aux.ev1, 0);
        skern<64><<<B_SZ, 256, 0, g_aux.s2>>>(x, h1p, s1p);
        dgemm<2048><<<dim3(8, 2, 16), 256, 0, g_aux.s2>>>(s1p, W1, pp, 64, 64);
        cudaEventRecord(g_aux.ej2, g_aux.s2);

        cin_mma64<<<B_SZ, 256, smM64>>>(x, h1p, wf1, b1, h2p);
        skern<64><<<B_SZ, 256>>>(x, h2p, s2p);
        dgemm<2048><<<dim3(8, 4, 16), 256>>>(s2p, W2, pp, 0, 128);

        cudaStreamWaitEvent(0, g_aux.ej1, 0);
        cudaStreamWaitEvent(0, g_aux.ej2, 0);
        reduce_out<<<B_SZ, 256>>>(pp, b0, b1, b2, out);
    } else {
        wfrag2<<<48, 256>>>(W0, W1, wf0, wf1);
        cin_mma32<<<B_SZ, 256, smM32>>>(x, wf0, b0, h1p);
        cin_mma64<<<B_SZ, 256, smM64>>>(x, h1p, wf1, b1, h2p);
        skern<32><<<B_SZ, 256>>>(x, x, s0p);
        skern<64><<<B_SZ, 256>>>(x, h1p, s1p);
        skern<64><<<B_SZ, 256>>>(x, h2p, s2p);
        dgemm<1024><<<dim3(8, 2, 16), 256>>>(s0p, W0, pp, 64, 0);
        dgemm<2048><<<dim3(8, 2, 16), 256>>>(s1p, W1, pp, 64, 64);
        dgemm<2048><<<dim3(8, 4, 16), 256>>>(s2p, W2, pp, 0, 128);
        reduce_out<<<B_SZ, 256>>>(pp, b0, b1, b2, out);
    }
}